// round 2
// baseline (speedup 1.0000x reference)
#include <cuda_runtime.h>
#include <math.h>

// Problem constants
#define BB 4
#define SS 1024
#define DD 1024
#define HH 16
#define HD 64
#define NEG_V 10000.0f

// Scratch (static device arrays; no allocation allowed)
__device__ float g_qkv[BB * SS * 3 * DD];     // [4096, 3072]
__device__ float g_am[BB * SS * DD];          // merged heads [4096, 1024]

// ---------------------------------------------------------------------------
// Generic SGEMM: C[M,N] = A[M,K] @ B[K,N] + bias[N]
// BM=128, BN=128, BK=8, TM=TN=8, 256 threads. M,N multiples of 128; K mult of 8.
// ---------------------------------------------------------------------------
__global__ __launch_bounds__(256) void sgemm_bias(
    const float* __restrict__ A, const float* __restrict__ B,
    const float* __restrict__ bias, float* __restrict__ C,
    int M, int N, int K, int lda, int ldb, int ldc)
{
    __shared__ float As[8][128];
    __shared__ float Bs[8][128];
    const int tid = threadIdx.x;
    const int tx = tid % 16;          // col group
    const int ty = tid / 16;          // row group
    const int rowStart = blockIdx.y * 128;
    const int colStart = blockIdx.x * 128;

    // A load: 128x8 tile, 1 float4/thread
    const int aRow = tid / 2;
    const int aCol4 = (tid % 2) * 4;
    // B load: 8x128 tile, 1 float4/thread
    const int bRow = tid / 32;
    const int bCol4 = (tid % 32) * 4;

    float acc[8][8];
#pragma unroll
    for (int i = 0; i < 8; i++)
#pragma unroll
        for (int j = 0; j < 8; j++) acc[i][j] = 0.f;

    for (int k0 = 0; k0 < K; k0 += 8) {
        float4 av = *reinterpret_cast<const float4*>(
            &A[(size_t)(rowStart + aRow) * lda + k0 + aCol4]);
        As[aCol4 + 0][aRow] = av.x;
        As[aCol4 + 1][aRow] = av.y;
        As[aCol4 + 2][aRow] = av.z;
        As[aCol4 + 3][aRow] = av.w;
        float4 bv = *reinterpret_cast<const float4*>(
            &B[(size_t)(k0 + bRow) * ldb + colStart + bCol4]);
        *reinterpret_cast<float4*>(&Bs[bRow][bCol4]) = bv;
        __syncthreads();
#pragma unroll
        for (int kk = 0; kk < 8; kk++) {
            float ar[8], br[8];
#pragma unroll
            for (int i = 0; i < 8; i++) ar[i] = As[kk][ty * 8 + i];
#pragma unroll
            for (int j = 0; j < 8; j++) br[j] = Bs[kk][tx * 8 + j];
#pragma unroll
            for (int i = 0; i < 8; i++)
#pragma unroll
                for (int j = 0; j < 8; j++) acc[i][j] += ar[i] * br[j];
        }
        __syncthreads();
    }

#pragma unroll
    for (int i = 0; i < 8; i++) {
        int r = rowStart + ty * 8 + i;
        float* crow = &C[(size_t)r * ldc + colStart + tx * 8];
        const float* brow = &bias[colStart + tx * 8];
#pragma unroll
        for (int j = 0; j < 8; j++) crow[j] = acc[i][j] + brow[j];
    }
}

// ---------------------------------------------------------------------------
// Batched QK^T with scale + causal mask epilogue.
// Per batch z = b*H + h: C[1024,1024], Q/K rows have stride 3072 in g_qkv.
// grid = (8, 8, 64), 256 threads. BK = 8 over Kdim = 64.
// Writes raw (masked, scaled) scores into Wout.
// ---------------------------------------------------------------------------
__global__ __launch_bounds__(256) void sgemm_qk(
    const float* __restrict__ qkv, const float* __restrict__ mask,
    float* __restrict__ Wout)
{
    __shared__ float As[8][128];
    __shared__ float Bs[8][128];
    const int tid = threadIdx.x;
    const int tx = tid % 16;
    const int ty = tid / 16;
    const int rowStart = blockIdx.y * 128;
    const int colStart = blockIdx.x * 128;
    const int z = blockIdx.z;
    const int b = z / HH;
    const int h = z % HH;

    const float* Qb = qkv + (size_t)b * SS * 3 * DD + h * HD;
    const float* Kb = Qb + DD;

    const int aRow = tid / 2;
    const int aCol4 = (tid % 2) * 4;

    float acc[8][8];
#pragma unroll
    for (int i = 0; i < 8; i++)
#pragma unroll
        for (int j = 0; j < 8; j++) acc[i][j] = 0.f;

    for (int k0 = 0; k0 < HD; k0 += 8) {
        // Q tile [128 rows][8 dims]
        float4 av = *reinterpret_cast<const float4*>(
            &Qb[(size_t)(rowStart + aRow) * (3 * DD) + k0 + aCol4]);
        As[aCol4 + 0][aRow] = av.x;
        As[aCol4 + 1][aRow] = av.y;
        As[aCol4 + 2][aRow] = av.z;
        As[aCol4 + 3][aRow] = av.w;
        // K tile (NT): Bs[k][j] = K[colStart+j][k]
        float4 bv = *reinterpret_cast<const float4*>(
            &Kb[(size_t)(colStart + aRow) * (3 * DD) + k0 + aCol4]);
        Bs[aCol4 + 0][aRow] = bv.x;
        Bs[aCol4 + 1][aRow] = bv.y;
        Bs[aCol4 + 2][aRow] = bv.z;
        Bs[aCol4 + 3][aRow] = bv.w;
        __syncthreads();
#pragma unroll
        for (int kk = 0; kk < 8; kk++) {
            float ar[8], br[8];
#pragma unroll
            for (int i = 0; i < 8; i++) ar[i] = As[kk][ty * 8 + i];
#pragma unroll
            for (int j = 0; j < 8; j++) br[j] = Bs[kk][tx * 8 + j];
#pragma unroll
            for (int i = 0; i < 8; i++)
#pragma unroll
                for (int j = 0; j < 8; j++) acc[i][j] += ar[i] * br[j];
        }
        __syncthreads();
    }

    const float* mrow = mask + (size_t)b * SS;
#pragma unroll
    for (int i = 0; i < 8; i++) {
        int r = rowStart + ty * 8 + i;
        float* crow = &Wout[((size_t)z * SS + r) * SS + colStart + tx * 8];
#pragma unroll
        for (int j = 0; j < 8; j++) {
            int c = colStart + tx * 8 + j;
            float v = (r >= c) ? acc[i][j] * 0.125f : -NEG_V;
            crow[j] = v + mrow[c];
        }
    }
}

// ---------------------------------------------------------------------------
// Row softmax in place over W: 65536 rows of 1024. One block (256 thr) per row.
// ---------------------------------------------------------------------------
__global__ __launch_bounds__(256) void softmax_rows(float* __restrict__ W)
{
    __shared__ float red[8];
    const int tid = threadIdx.x;
    float* row = W + (size_t)blockIdx.x * SS;

    float4 v = *reinterpret_cast<const float4*>(&row[tid * 4]);
    float m = fmaxf(fmaxf(v.x, v.y), fmaxf(v.z, v.w));
#pragma unroll
    for (int o = 16; o > 0; o >>= 1) m = fmaxf(m, __shfl_xor_sync(0xffffffffu, m, o));
    if ((tid & 31) == 0) red[tid >> 5] = m;
    __syncthreads();
    if (tid < 32) {
        float t = (tid < 8) ? red[tid] : -INFINITY;
#pragma unroll
        for (int o = 4; o > 0; o >>= 1) t = fmaxf(t, __shfl_xor_sync(0xffffffffu, t, o));
        if (tid == 0) red[0] = t;
    }
    __syncthreads();
    m = red[0];

    float4 e;
    e.x = __expf(v.x - m);
    e.y = __expf(v.y - m);
    e.z = __expf(v.z - m);
    e.w = __expf(v.w - m);
    float s = e.x + e.y + e.z + e.w;
#pragma unroll
    for (int o = 16; o > 0; o >>= 1) s += __shfl_xor_sync(0xffffffffu, s, o);
    __syncthreads();
    if ((tid & 31) == 0) red[tid >> 5] = s;
    __syncthreads();
    if (tid < 32) {
        float t = (tid < 8) ? red[tid] : 0.f;
#pragma unroll
        for (int o = 4; o > 0; o >>= 1) t += __shfl_xor_sync(0xffffffffu, t, o);
        if (tid == 0) red[0] = t;
    }
    __syncthreads();
    float inv = 1.0f / red[0];

    e.x *= inv; e.y *= inv; e.z *= inv; e.w *= inv;
    *reinterpret_cast<float4*>(&row[tid * 4]) = e;
}

// ---------------------------------------------------------------------------
// Batched AV: per z = b*H+h, C[1024,64] = W_z[1024,1024] @ V_z[1024,64].
// BM=128, BN=64, BK=16, TM=8, TN=4, 256 threads. grid = (1, 8, 64).
// Writes merged-head layout into g_am[b*S + row][h*64 + col].
// ---------------------------------------------------------------------------
__global__ __launch_bounds__(256) void sgemm_av(
    const float* __restrict__ W, const float* __restrict__ qkv,
    float* __restrict__ Am)
{
    __shared__ float As[16][128];
    __shared__ float Bs[16][64];
    const int tid = threadIdx.x;
    const int tx = tid % 16;   // col group (4 cols each)
    const int ty = tid / 16;   // row group (8 rows each)
    const int rowStart = blockIdx.y * 128;
    const int z = blockIdx.z;
    const int b = z / HH;
    const int h = z % HH;

    const float* Wb = W + (size_t)z * SS * SS;
    const float* Vb = qkv + (size_t)b * SS * 3 * DD + 2 * DD + h * HD;

    float acc[8][4];
#pragma unroll
    for (int i = 0; i < 8; i++)
#pragma unroll
        for (int j = 0; j < 4; j++) acc[i][j] = 0.f;

    const int bRow = tid / 16;     // 0..15
    const int bCol4 = (tid % 16) * 4;

    for (int k0 = 0; k0 < SS; k0 += 16) {
        // A tile 128x16 = 512 float4, 2 per thread
#pragma unroll
        for (int t = 0; t < 2; t++) {
            int lin = tid * 2 + t;
            int aRow = lin / 4;
            int aCol4 = (lin % 4) * 4;
            float4 av = *reinterpret_cast<const float4*>(
                &Wb[(size_t)(rowStart + aRow) * SS + k0 + aCol4]);
            As[aCol4 + 0][aRow] = av.x;
            As[aCol4 + 1][aRow] = av.y;
            As[aCol4 + 2][aRow] = av.z;
            As[aCol4 + 3][aRow] = av.w;
        }
        // B tile 16x64 = 256 float4, 1 per thread
        float4 bv = *reinterpret_cast<const float4*>(
            &Vb[(size_t)(k0 + bRow) * (3 * DD) + bCol4]);
        *reinterpret_cast<float4*>(&Bs[bRow][bCol4]) = bv;
        __syncthreads();
#pragma unroll
        for (int kk = 0; kk < 16; kk++) {
            float ar[8], br[4];
#pragma unroll
            for (int i = 0; i < 8; i++) ar[i] = As[kk][ty * 8 + i];
#pragma unroll
            for (int j = 0; j < 4; j++) br[j] = Bs[kk][tx * 4 + j];
#pragma unroll
            for (int i = 0; i < 8; i++)
#pragma unroll
                for (int j = 0; j < 4; j++) acc[i][j] += ar[i] * br[j];
        }
        __syncthreads();
    }

#pragma unroll
    for (int i = 0; i < 8; i++) {
        int r = rowStart + ty * 8 + i;
        float* orow = &Am[((size_t)b * SS + r) * DD + h * HD + tx * 4];
#pragma unroll
        for (int j = 0; j < 4; j++) orow[j] = acc[i][j];
    }
}

// ---------------------------------------------------------------------------
extern "C" void kernel_launch(void* const* d_in, const int* in_sizes, int n_in,
                              void* d_out, int out_size)
{
    const float* x      = (const float*)d_in[0];   // [4,1024,1024]
    const float* mask   = (const float*)d_in[1];   // [4,1,1,1024]
    const float* w_attn = (const float*)d_in[2];   // [1024,3072]
    const float* b_attn = (const float*)d_in[3];   // [1,3072]
    const float* w_proj = (const float*)d_in[4];   // [1024,1024]
    const float* b_proj = (const float*)d_in[5];   // [1,1024]

    float* out = (float*)d_out;
    float* a_out = out;                                  // [4,1024,1024]
    float* w_out = out + (size_t)BB * SS * DD;           // [4,16,1024,1024]

    float* qkv = nullptr;
    float* am = nullptr;
    cudaGetSymbolAddress((void**)&qkv, g_qkv);
    cudaGetSymbolAddress((void**)&am, g_am);

    // 1) qkv = x @ w_attn + b_attn   (4096 x 3072 x 1024)
    {
        dim3 grid(3 * DD / 128, BB * SS / 128);
        sgemm_bias<<<grid, 256>>>(x, w_attn, b_attn, qkv,
                                  BB * SS, 3 * DD, DD, DD, 3 * DD, 3 * DD);
    }
    // 2) scores = scale * Q@K^T with causal mask (+mask) -> w_out
    {
        dim3 grid(SS / 128, SS / 128, BB * HH);
        sgemm_qk<<<grid, 256>>>(qkv, mask, w_out);
    }
    // 3) softmax rows in place
    {
        softmax_rows<<<BB * HH * SS, 256>>>(w_out);
    }
    // 4) a_heads = W @ V, merged into g_am
    {
        dim3 grid(1, SS / 128, BB * HH);
        sgemm_av<<<grid, 256>>>(w_out, qkv, am);
    }
    // 5) a = a_merged @ w_proj + b_proj -> a_out
    {
        dim3 grid(DD / 128, BB * SS / 128);
        sgemm_bias<<<grid, 256>>>(am, w_proj, b_proj, a_out,
                                  BB * SS, DD, DD, DD, DD, DD);
    }
}

// round 3
// speedup vs baseline: 1.4361x; 1.4361x over previous
#include <cuda_runtime.h>
#include <math.h>
#include <stdint.h>

// Problem constants
#define BB 4
#define SS 1024
#define DD 1024
#define HH 16
#define HD 64
#define NEG_V 10000.0f

// Scratch (static device arrays; no allocation allowed)
__device__ float g_qkv[BB * SS * 3 * DD];     // [4096, 3072]
__device__ float g_am[BB * SS * DD];          // merged heads [4096, 1024]

// ---------------------------------------------------------------------------
// tf32 helpers
// ---------------------------------------------------------------------------
__device__ __forceinline__ uint32_t f2tf(float f) {
    uint32_t u;
    asm("cvt.rna.tf32.f32 %0, %1;" : "=r"(u) : "f"(f));
    return u;
}

__device__ __forceinline__ void mma8(float* c, const uint32_t* a, const uint32_t* b) {
    asm volatile(
        "mma.sync.aligned.m16n8k8.row.col.f32.tf32.tf32.f32 "
        "{%0,%1,%2,%3}, {%4,%5,%6,%7}, {%8,%9}, {%0,%1,%2,%3};\n"
        : "+f"(c[0]), "+f"(c[1]), "+f"(c[2]), "+f"(c[3])
        : "r"(a[0]), "r"(a[1]), "r"(a[2]), "r"(a[3]), "r"(b[0]), "r"(b[1]));
}

// Fragment-pack index helpers (m16n8k8):
//  A value (r in 0..15 within m16 tile, kk in 0..7 within k8):
//    lane = ((r&7)<<2) | (kk&3),  reg = (r>>3) | ((kk>>2)<<1)   -> 4 regs, LDS.128
//  B value (n col c in 0..7, kk in 0..7):
//    lane = (c<<2) | (kk&3),      reg = kk>>2                   -> 2 regs, LDS.64

// ---------------------------------------------------------------------------
// Generic tf32 GEMM: C[M,N] = A[M,K] @ B[K,N] + bias[N]
// BM=128, BN=128, BK=16, 256 threads (8 warps: 4 in M x 2 in N, warp 32x64)
// ---------------------------------------------------------------------------
__global__ __launch_bounds__(256) void gemm_tf32_bias(
    const float* __restrict__ A, const float* __restrict__ B,
    const float* __restrict__ bias, float* __restrict__ C,
    int K, int lda, int ldb, int ldc)
{
    __shared__ __align__(16) uint32_t Ap[2][8][32][4];   // [ksub][mi][lane][reg]
    __shared__ __align__(16) uint32_t Bp[2][16][32][2];  // [ksub][ni][lane][reg]

    const int tid = threadIdx.x;
    const int lane = tid & 31;
    const int warp = tid >> 5;
    const int wm = warp & 3, wn = warp >> 2;
    const int rowStart = blockIdx.y * 128;
    const int colStart = blockIdx.x * 128;

    float acc[2][8][4];
#pragma unroll
    for (int mi = 0; mi < 2; mi++)
#pragma unroll
        for (int ni = 0; ni < 8; ni++)
#pragma unroll
            for (int r = 0; r < 4; r++) acc[mi][ni][r] = 0.f;

    float4 aR[2], bR[2];

#define G_LOADG(kb) do {                                                          \
    _Pragma("unroll")                                                             \
    for (int i = 0; i < 2; i++) {                                                 \
        int lin = tid * 2 + i;                                                    \
        aR[i] = *reinterpret_cast<const float4*>(                                 \
            &A[(size_t)(rowStart + (lin >> 2)) * lda + (kb) + ((lin & 3) << 2)]); \
        bR[i] = *reinterpret_cast<const float4*>(                                 \
            &B[(size_t)((kb) + (lin >> 5)) * ldb + colStart + ((lin & 31) << 2)]);\
    } } while (0)

#define G_STORES() do {                                                           \
    _Pragma("unroll")                                                             \
    for (int i = 0; i < 2; i++) {                                                 \
        int lin = tid * 2 + i;                                                    \
        int m = lin >> 2; int k0l = (lin & 3) << 2; int mi = m >> 4; int r = m & 15; \
        float va[4] = {aR[i].x, aR[i].y, aR[i].z, aR[i].w};                       \
        _Pragma("unroll")                                                         \
        for (int j = 0; j < 4; j++) {                                             \
            int k = k0l + j; int kk = k & 7; int ks = k >> 3;                     \
            Ap[ks][mi][((r & 7) << 2) | (kk & 3)][(r >> 3) | ((kk >> 2) << 1)] = f2tf(va[j]); \
        }                                                                         \
        int kB = lin >> 5; int n0 = (lin & 31) << 2; int kkB = kB & 7; int ksB = kB >> 3; \
        float vb[4] = {bR[i].x, bR[i].y, bR[i].z, bR[i].w};                       \
        _Pragma("unroll")                                                         \
        for (int j = 0; j < 4; j++) {                                             \
            int n = n0 + j;                                                       \
            Bp[ksB][n >> 3][((n & 7) << 2) | (kkB & 3)][kkB >> 2] = f2tf(vb[j]);  \
        }                                                                         \
    } } while (0)

#define G_COMPUTE() do {                                                          \
    _Pragma("unroll")                                                             \
    for (int ks = 0; ks < 2; ks++) {                                              \
        uint32_t af[2][4]; uint32_t bf[8][2];                                     \
        _Pragma("unroll")                                                         \
        for (int mi = 0; mi < 2; mi++)                                            \
            *reinterpret_cast<uint4*>(af[mi]) =                                   \
                *reinterpret_cast<const uint4*>(Ap[ks][wm * 2 + mi][lane]);       \
        _Pragma("unroll")                                                         \
        for (int ni = 0; ni < 8; ni++)                                            \
            *reinterpret_cast<uint2*>(bf[ni]) =                                   \
                *reinterpret_cast<const uint2*>(Bp[ks][wn * 8 + ni][lane]);       \
        _Pragma("unroll")                                                         \
        for (int mi = 0; mi < 2; mi++)                                            \
            _Pragma("unroll")                                                     \
            for (int ni = 0; ni < 8; ni++)                                        \
                mma8(acc[mi][ni], af[mi], bf[ni]);                                \
    } } while (0)

    G_LOADG(0);
    G_STORES();
    __syncthreads();
    for (int kb = 16; kb < K; kb += 16) {
        G_LOADG(kb);
        G_COMPUTE();
        __syncthreads();
        G_STORES();
        __syncthreads();
    }
    G_COMPUTE();

    // epilogue
#pragma unroll
    for (int mi = 0; mi < 2; mi++)
#pragma unroll
        for (int ni = 0; ni < 8; ni++) {
            int row = rowStart + wm * 32 + mi * 16 + (lane >> 2);
            int col = colStart + wn * 64 + ni * 8 + (lane & 3) * 2;
            float b0 = bias[col], b1 = bias[col + 1];
            C[(size_t)row * ldc + col]           = acc[mi][ni][0] + b0;
            C[(size_t)row * ldc + col + 1]       = acc[mi][ni][1] + b1;
            C[(size_t)(row + 8) * ldc + col]     = acc[mi][ni][2] + b0;
            C[(size_t)(row + 8) * ldc + col + 1] = acc[mi][ni][3] + b1;
        }
}

// ---------------------------------------------------------------------------
// QK^T (tf32 mma) with scale + causal mask + additive mask epilogue.
// Per z = b*H+h: scores[1024,1024]. 128x128 tile, K-dim = 64 (4 chunks of 16).
// ---------------------------------------------------------------------------
__global__ __launch_bounds__(256) void qk_tf32(
    const float* __restrict__ qkv, const float* __restrict__ mask,
    float* __restrict__ Wout)
{
    __shared__ __align__(16) uint32_t Ap[2][8][32][4];
    __shared__ __align__(16) uint32_t Bp[2][16][32][2];

    const int tid = threadIdx.x;
    const int lane = tid & 31;
    const int warp = tid >> 5;
    const int wm = warp & 3, wn = warp >> 2;
    const int rowStart = blockIdx.y * 128;
    const int colStart = blockIdx.x * 128;
    const int z = blockIdx.z;
    const int b = z / HH;
    const int h = z % HH;

    const float* Qb = qkv + (size_t)b * SS * 3 * DD + h * HD;
    const float* Kb = Qb + DD;

    float acc[2][8][4];
#pragma unroll
    for (int mi = 0; mi < 2; mi++)
#pragma unroll
        for (int ni = 0; ni < 8; ni++)
#pragma unroll
            for (int r = 0; r < 4; r++) acc[mi][ni][r] = 0.f;

    float4 aR[2], bR[2];

#define QK_LOADG(kb) do {                                                         \
    _Pragma("unroll")                                                             \
    for (int i = 0; i < 2; i++) {                                                 \
        int lin = tid * 2 + i;                                                    \
        aR[i] = *reinterpret_cast<const float4*>(                                 \
            &Qb[(size_t)(rowStart + (lin >> 2)) * (3 * DD) + (kb) + ((lin & 3) << 2)]); \
        bR[i] = *reinterpret_cast<const float4*>(                                 \
            &Kb[(size_t)(colStart + (lin >> 2)) * (3 * DD) + (kb) + ((lin & 3) << 2)]); \
    } } while (0)

#define QK_STORES() do {                                                          \
    _Pragma("unroll")                                                             \
    for (int i = 0; i < 2; i++) {                                                 \
        int lin = tid * 2 + i;                                                    \
        int m = lin >> 2; int k0l = (lin & 3) << 2; int mi = m >> 4; int r = m & 15; \
        float va[4] = {aR[i].x, aR[i].y, aR[i].z, aR[i].w};                       \
        float vb[4] = {bR[i].x, bR[i].y, bR[i].z, bR[i].w};                       \
        _Pragma("unroll")                                                         \
        for (int j = 0; j < 4; j++) {                                             \
            int k = k0l + j; int kk = k & 7; int ks = k >> 3;                     \
            Ap[ks][mi][((r & 7) << 2) | (kk & 3)][(r >> 3) | ((kk >> 2) << 1)] = f2tf(va[j]); \
            /* B: n = m (this lin indexes K-matrix row = output col) */           \
            Bp[ks][m >> 3][((m & 7) << 2) | (kk & 3)][kk >> 2] = f2tf(vb[j]);     \
        }                                                                         \
    } } while (0)

    QK_LOADG(0);
    QK_STORES();
    __syncthreads();
    for (int kb = 16; kb < HD; kb += 16) {
        QK_LOADG(kb);
        G_COMPUTE();
        __syncthreads();
        QK_STORES();
        __syncthreads();
    }
    G_COMPUTE();

    const float* mrow = mask + (size_t)b * SS;
#pragma unroll
    for (int mi = 0; mi < 2; mi++)
#pragma unroll
        for (int ni = 0; ni < 8; ni++) {
            int row0 = rowStart + wm * 32 + mi * 16 + (lane >> 2);
            int col = colStart + wn * 64 + ni * 8 + (lane & 3) * 2;
            float m0 = mrow[col], m1 = mrow[col + 1];
#pragma unroll
            for (int half = 0; half < 2; half++) {
                int row = row0 + half * 8;
                float v0 = (row >= col)     ? acc[mi][ni][half * 2 + 0] * 0.125f : -NEG_V;
                float v1 = (row >= col + 1) ? acc[mi][ni][half * 2 + 1] * 0.125f : -NEG_V;
                float* crow = &Wout[((size_t)z * SS + row) * SS + col];
                crow[0] = v0 + m0;
                crow[1] = v1 + m1;
            }
        }
}

// ---------------------------------------------------------------------------
// Row softmax in place over W: 65536 rows of 1024. One block (256 thr) per row.
// ---------------------------------------------------------------------------
__global__ __launch_bounds__(256) void softmax_rows(float* __restrict__ W)
{
    __shared__ float red[8];
    const int tid = threadIdx.x;
    float* row = W + (size_t)blockIdx.x * SS;

    float4 v = *reinterpret_cast<const float4*>(&row[tid * 4]);
    float m = fmaxf(fmaxf(v.x, v.y), fmaxf(v.z, v.w));
#pragma unroll
    for (int o = 16; o > 0; o >>= 1) m = fmaxf(m, __shfl_xor_sync(0xffffffffu, m, o));
    if ((tid & 31) == 0) red[tid >> 5] = m;
    __syncthreads();
    if (tid < 32) {
        float t = (tid < 8) ? red[tid] : -INFINITY;
#pragma unroll
        for (int o = 4; o > 0; o >>= 1) t = fmaxf(t, __shfl_xor_sync(0xffffffffu, t, o));
        if (tid == 0) red[0] = t;
    }
    __syncthreads();
    m = red[0];

    float4 e;
    e.x = __expf(v.x - m);
    e.y = __expf(v.y - m);
    e.z = __expf(v.z - m);
    e.w = __expf(v.w - m);
    float s = e.x + e.y + e.z + e.w;
#pragma unroll
    for (int o = 16; o > 0; o >>= 1) s += __shfl_xor_sync(0xffffffffu, s, o);
    __syncthreads();
    if ((tid & 31) == 0) red[tid >> 5] = s;
    __syncthreads();
    if (tid < 32) {
        float t = (tid < 8) ? red[tid] : 0.f;
#pragma unroll
        for (int o = 4; o > 0; o >>= 1) t += __shfl_xor_sync(0xffffffffu, t, o);
        if (tid == 0) red[0] = t;
    }
    __syncthreads();
    float inv = 1.0f / red[0];

    e.x *= inv; e.y *= inv; e.z *= inv; e.w *= inv;
    *reinterpret_cast<float4*>(&row[tid * 4]) = e;
}

// ---------------------------------------------------------------------------
// AV (tf32 mma): per z = b*H+h: C[1024,64] = W_z[1024,1024] @ V_z[1024,64].
// BM=128, BN=64, BK=16, 256 threads (8 warps, each 16 rows x 64 cols).
// Writes merged-head layout into g_am.
// ---------------------------------------------------------------------------
__global__ __launch_bounds__(256) void av_tf32(
    const float* __restrict__ W, const float* __restrict__ qkv,
    float* __restrict__ Am)
{
    __shared__ __align__(16) uint32_t Ap[2][8][32][4];
    __shared__ __align__(16) uint32_t Bp[2][8][32][2];

    const int tid = threadIdx.x;
    const int lane = tid & 31;
    const int warp = tid >> 5;
    const int rowStart = blockIdx.x * 128;
    const int z = blockIdx.y;
    const int b = z / HH;
    const int h = z % HH;

    const float* Wb = W + (size_t)z * SS * SS;
    const float* Vb = qkv + (size_t)b * SS * 3 * DD + 2 * DD + h * HD;

    float acc[8][4];
#pragma unroll
    for (int ni = 0; ni < 8; ni++)
#pragma unroll
        for (int r = 0; r < 4; r++) acc[ni][r] = 0.f;

    float4 aR[2], bR;

#define AV_LOADG(kb) do {                                                         \
    _Pragma("unroll")                                                             \
    for (int i = 0; i < 2; i++) {                                                 \
        int lin = tid * 2 + i;                                                    \
        aR[i] = *reinterpret_cast<const float4*>(                                 \
            &Wb[(size_t)(rowStart + (lin >> 2)) * SS + (kb) + ((lin & 3) << 2)]); \
    }                                                                             \
    bR = *reinterpret_cast<const float4*>(                                        \
        &Vb[(size_t)((kb) + (tid >> 4)) * (3 * DD) + ((tid & 15) << 2)]);         \
    } while (0)

#define AV_STORES() do {                                                          \
    _Pragma("unroll")                                                             \
    for (int i = 0; i < 2; i++) {                                                 \
        int lin = tid * 2 + i;                                                    \
        int m = lin >> 2; int k0l = (lin & 3) << 2; int mi = m >> 4; int r = m & 15; \
        float va[4] = {aR[i].x, aR[i].y, aR[i].z, aR[i].w};                       \
        _Pragma("unroll")                                                         \
        for (int j = 0; j < 4; j++) {                                             \
            int k = k0l + j; int kk = k & 7; int ks = k >> 3;                     \
            Ap[ks][mi][((r & 7) << 2) | (kk & 3)][(r >> 3) | ((kk >> 2) << 1)] = f2tf(va[j]); \
        }                                                                         \
    }                                                                             \
    {                                                                             \
        int kB = tid >> 4; int n0 = (tid & 15) << 2;                              \
        int kkB = kB & 7; int ksB = kB >> 3;                                      \
        float vb[4] = {bR.x, bR.y, bR.z, bR.w};                                   \
        _Pragma("unroll")                                                         \
        for (int j = 0; j < 4; j++) {                                             \
            int n = n0 + j;                                                       \
            Bp[ksB][n >> 3][((n & 7) << 2) | (kkB & 3)][kkB >> 2] = f2tf(vb[j]);  \
        }                                                                         \
    } } while (0)

#define AV_COMPUTE() do {                                                         \
    _Pragma("unroll")                                                             \
    for (int ks = 0; ks < 2; ks++) {                                              \
        uint32_t af[4]; uint32_t bf[8][2];                                        \
        *reinterpret_cast<uint4*>(af) =                                           \
            *reinterpret_cast<const uint4*>(Ap[ks][warp][lane]);                  \
        _Pragma("unroll")                                                         \
        for (int ni = 0; ni < 8; ni++)                                            \
            *reinterpret_cast<uint2*>(bf[ni]) =                                   \
                *reinterpret_cast<const uint2*>(Bp[ks][ni][lane]);                \
        _Pragma("unroll")                                                         \
        for (int ni = 0; ni < 8; ni++)                                            \
            mma8(acc[ni], af, bf[ni]);                                            \
    } } while (0)

    AV_LOADG(0);
    AV_STORES();
    __syncthreads();
    for (int kb = 16; kb < SS; kb += 16) {
        AV_LOADG(kb);
        AV_COMPUTE();
        __syncthreads();
        AV_STORES();
        __syncthreads();
    }
    AV_COMPUTE();

#pragma unroll
    for (int ni = 0; ni < 8; ni++) {
        int row = rowStart + warp * 16 + (lane >> 2);
        int col = h * HD + ni * 8 + (lane & 3) * 2;
        float* o0 = &Am[((size_t)b * SS + row) * DD + col];
        float* o1 = &Am[((size_t)b * SS + row + 8) * DD + col];
        o0[0] = acc[ni][0]; o0[1] = acc[ni][1];
        o1[0] = acc[ni][2]; o1[1] = acc[ni][3];
    }
}

// ---------------------------------------------------------------------------
extern "C" void kernel_launch(void* const* d_in, const int* in_sizes, int n_in,
                              void* d_out, int out_size)
{
    const float* x      = (const float*)d_in[0];   // [4,1024,1024]
    const float* mask   = (const float*)d_in[1];   // [4,1,1,1024]
    const float* w_attn = (const float*)d_in[2];   // [1024,3072]
    const float* b_attn = (const float*)d_in[3];   // [1,3072]
    const float* w_proj = (const float*)d_in[4];   // [1024,1024]
    const float* b_proj = (const float*)d_in[5];   // [1,1024]

    float* out = (float*)d_out;
    float* a_out = out;                                  // [4,1024,1024]
    float* w_out = out + (size_t)BB * SS * DD;           // [4,16,1024,1024]

    float* qkv = nullptr;
    float* am = nullptr;
    cudaGetSymbolAddress((void**)&qkv, g_qkv);
    cudaGetSymbolAddress((void**)&am, g_am);

    // 1) qkv = x @ w_attn + b_attn   (4096 x 3072 x 1024)
    {
        dim3 grid(3 * DD / 128, BB * SS / 128);
        gemm_tf32_bias<<<grid, 256>>>(x, w_attn, b_attn, qkv,
                                      DD, DD, 3 * DD, 3 * DD);
    }
    // 2) scores = scale * Q@K^T with causal mask (+mask) -> w_out
    {
        dim3 grid(SS / 128, SS / 128, BB * HH);
        qk_tf32<<<grid, 256>>>(qkv, mask, w_out);
    }
    // 3) softmax rows in place
    {
        softmax_rows<<<BB * HH * SS, 256>>>(w_out);
    }
    // 4) a_heads = W @ V, merged into g_am
    {
        dim3 grid(SS / 128, BB * HH);
        av_tf32<<<grid, 256>>>(w_out, qkv, am);
    }
    // 5) a = a_merged @ w_proj + b_proj -> a_out
    {
        dim3 grid(DD / 128, BB * SS / 128);
        gemm_tf32_bias<<<grid, 256>>>(am, w_proj, b_proj, a_out,
                                      DD, DD, DD, DD);
    }
}